// round 17
// baseline (speedup 1.0000x reference)
#include <cuda_runtime.h>
#include <math.h>

#define BB 2
#define HH 720
#define WW 1280
#define HW (HH*WW)
#define NPIX (BB*HW)
#define EPSF 1e-7f

// Scratch: splat accumulators, chunk layout [d0b0][d0b1][d1b0][d1b1], 4ch each
__device__ __align__(16) float g_acc[(size_t)2 * BB * HW * 4];

// ---------------------------------------------------------------------------
// Splat kernel: ONE BATCH per launch, both warp directions per thread.
// All pointers pre-offset to the batch. 1 px/thread; RED.E.128 per corner.
// ---------------------------------------------------------------------------
__global__ void __launch_bounds__(256) splat_batch_kernel(
    const float* __restrict__ imgA, const float* __restrict__ flA,
    const float* __restrict__ zA, float4* __restrict__ accA,
    const float* __restrict__ imgB, const float* __restrict__ flB,
    const float* __restrict__ zB, float4* __restrict__ accB)
{
    int p = blockIdx.x * blockDim.x + threadIdx.x;
    if (p >= HW) return;
    int y = p / WW;
    int x = p - y * WW;

#pragma unroll
    for (int d = 0; d < 2; ++d) {
        const float* img = d ? imgB : imgA;
        const float* fl  = d ? flB : flA;
        const float* zz  = d ? zB : zA;
        float4* acc      = d ? accB : accA;

        float fx = (float)x + 0.5f * fl[(size_t)HW + p];
        float fy = (float)y + 0.5f * fl[p];
        float w  = __expf(zz[p]);
        float vr = img[p] * w;
        float vg = img[(size_t)HW + p] * w;
        float vb = img[(size_t)2 * HW + p] * w;

        float x0f = floorf(fx), y0f = floorf(fy);
        int ix0 = (int)x0f, iy0 = (int)y0f;
        float ax = fx - x0f, ay = fy - y0f;

#pragma unroll
        for (int cy = 0; cy < 2; ++cy) {
            int ty = iy0 + cy;
            if ((unsigned)ty >= (unsigned)HH) continue;
            float wy = cy ? ay : (1.0f - ay);
#pragma unroll
            for (int cx = 0; cx < 2; ++cx) {
                int tx = ix0 + cx;
                if ((unsigned)tx >= (unsigned)WW) continue;
                float wt = wy * (cx ? ax : (1.0f - ax));
                atomicAdd(acc + ((size_t)ty * WW + tx),
                          make_float4(vr * wt, vg * wt, vb * wt, w * wt));
            }
        }
    }
}

// ---------------------------------------------------------------------------
// Flow channels (12-15): out = 0.5 * flow. DRAM-bound; hidden under splats.
// ---------------------------------------------------------------------------
#define FQ (BB * 2 * HW / 4)
__global__ void __launch_bounds__(256) flow_copy_kernel(
    const float4* __restrict__ f0, const float4* __restrict__ f1,
    float4* __restrict__ out)
{
    int i = blockIdx.x * blockDim.x + threadIdx.x;
    if (i >= FQ) return;
    const int CH4 = HW / 4;
    int b = i / (2 * CH4);
    int rem = i - b * (2 * CH4);
    int c = rem / CH4;
    int p4 = rem - c * CH4;

    float4 q0 = __ldcs(f0 + i);
    float4 q1 = __ldcs(f1 + i);
    float4 h0 = make_float4(0.5f*q0.x, 0.5f*q0.y, 0.5f*q0.z, 0.5f*q0.w);
    float4 h1 = make_float4(0.5f*q1.x, 0.5f*q1.y, 0.5f*q1.z, 0.5f*q1.w);
    __stcs(out + (size_t)(b * 18 + 12 + c) * CH4 + p4, h0);
    __stcs(out + (size_t)(b * 18 + 14 + c) * CH4 + p4, h1);
}

// ---------------------------------------------------------------------------
// Fused normalize + morphological open + compose (R16 structure), ONE BATCH
// per launch (batch index passed as argument). 64x16 tile, 32x16 threads,
// 2 px/thread, buffer overlay, ring-enumerated halo, regs clamped to 32.
// ---------------------------------------------------------------------------
#define TPX 64
#define TBX 32
#define TTY 16
#define RMAX 4
#define NT (TBX * TTY)   // 512

#define NIN_F (2 * (TTY + 4 * RMAX) * (TPX + 4 * RMAX))  // 5120 floats
#define NHM_F (2 * (TTY + 4 * RMAX) * (TPX + 2 * RMAX))  // 4608 floats
#define DYN_SMEM_BYTES ((NIN_F + NHM_F) * (int)sizeof(float))   // 38912 B

template<int R>
__device__ __forceinline__ void open_body(
    float* __restrict__ BufA, float* __restrict__ BufB,
    int b, float* __restrict__ out)
{
    constexpr int INW = TPX + 4 * R;
    constexpr int INH = TTY + 4 * R;
    constexpr int HMW = TPX + 2 * R;   // even
    constexpr int EH  = TTY + 2 * R;   // even
    constexpr int WIN = 2 * R;

    const float PINF = __int_as_float(0x7f800000);
    const float NINF = __int_as_float(0xff800000);

    int ox = blockIdx.x * TPX;
    int oy = blockIdx.y * TTY;
    int tid = threadIdx.y * TBX + threadIdx.x;
    int txx = threadIdx.x, tyy = threadIdx.y;

#define S_IN(m, iy, ix) BufA[(m) * (INH * INW) + (iy) * INW + (ix)]
#define S_ER(m, ey, hx) BufA[(m) * (EH * HMW) + (ey) * HMW + (hx)]
#define S_HM(m, iy, hx) BufB[(m) * (INH * HMW) + (iy) * HMW + (hx)]
#define S_HX(m, ey, xx) BufB[(m) * (EH * TPX) + (ey) * TPX + (xx)]

    int gx0 = ox + 2 * txx;
    int gy  = oy + tyy;
    size_t p0 = (size_t)gy * WW + gx0;

    // acc chunk layout: [d0b0][d0b1][d1b0][d1b1]
    const float* w0 = g_acc + ((size_t)(0 * BB + b) * HW << 2) + 3;
    const float* w1 = g_acc + ((size_t)(1 * BB + b) * HW << 2) + 3;

    // Stage 1a: center w values from direct scalar loads (2 px, 2 masks)
    {
        int cy = tyy + 2 * R, cx = 2 * txx + 2 * R;
        S_IN(0, cy, cx)     = w0[p0 << 2];
        S_IN(0, cy, cx + 1) = w0[(p0 + 1) << 2];
        S_IN(1, cy, cx)     = w1[p0 << 2];
        S_IN(1, cy, cx + 1) = w1[(p0 + 1) << 2];
    }

    // Stage 1b: halo RING enumerated directly; +inf outside image
    if (R > 0) {
        constexpr int TB   = 2 * R * INW;
        constexpr int LR   = TTY * 2 * R;
        constexpr int RING = 2 * TB + 2 * LR;
        for (int idx = tid; idx < RING; idx += NT) {
            int iy, ix;
            if (idx < TB) {
                iy = idx / INW;
                ix = idx - iy * INW;
            } else if (idx < 2 * TB) {
                int j = idx - TB;
                iy = TTY + 2 * R + j / INW;
                ix = j - (j / INW) * INW;
            } else if (idx < 2 * TB + LR) {
                int j = idx - 2 * TB;
                iy = 2 * R + j / (2 * R);
                ix = j - (j / (2 * R)) * (2 * R);
            } else {
                int j = idx - 2 * TB - LR;
                iy = 2 * R + j / (2 * R);
                ix = TPX + 2 * R + (j - (j / (2 * R)) * (2 * R));
            }
            int hy = oy - 2 * R + iy;
            int hx = ox - 2 * R + ix;
            float v0 = PINF, v1 = PINF;
            if ((unsigned)hy < (unsigned)HH && (unsigned)hx < (unsigned)WW) {
                size_t o = ((size_t)hy * WW + hx) << 2;
                v0 = w0[o];
                v1 = w1[o];
            }
            S_IN(0, iy, ix) = v0;
            S_IN(1, iy, ix) = v1;
        }
    }
    __syncthreads();

    // Stage 2: horizontal min, paired outputs
    {
        constexpr int HMW2 = HMW / 2;
        for (int idx = tid; idx < INH * HMW2; idx += NT) {
            int iy = idx / HMW2;
            int hx = (idx - iy * HMW2) * 2;
            float c0 = S_IN(0, iy, hx + 1);
            float c1 = S_IN(1, iy, hx + 1);
#pragma unroll
            for (int dd = 2; dd <= WIN; ++dd) {
                c0 = fminf(c0, S_IN(0, iy, hx + dd));
                c1 = fminf(c1, S_IN(1, iy, hx + dd));
            }
            S_HM(0, iy, hx)     = fminf(S_IN(0, iy, hx), c0);
            S_HM(1, iy, hx)     = fminf(S_IN(1, iy, hx), c1);
            S_HM(0, iy, hx + 1) = fminf(c0, S_IN(0, iy, hx + WIN + 1));
            S_HM(1, iy, hx + 1) = fminf(c1, S_IN(1, iy, hx + WIN + 1));
        }
    }
    __syncthreads();   // s_in dead -> BufA reusable as s_er

    // Stage 3: vertical min -> erosion; OOB -> -inf
    {
        constexpr int EH2 = EH / 2;
        for (int idx = tid; idx < EH2 * HMW; idx += NT) {
            int ep = idx / HMW;
            int hx = idx - ep * HMW;
            int ey = ep * 2;
            int hgx = ox - R + hx;
            bool colok = (unsigned)hgx < (unsigned)WW;
            int hy0 = oy - R + ey;
            float c0 = S_HM(0, ey + 1, hx);
            float c1 = S_HM(1, ey + 1, hx);
#pragma unroll
            for (int dd = 2; dd <= WIN; ++dd) {
                c0 = fminf(c0, S_HM(0, ey + dd, hx));
                c1 = fminf(c1, S_HM(1, ey + dd, hx));
            }
            bool ok0 = colok && ((unsigned)hy0 < (unsigned)HH);
            bool ok1 = colok && ((unsigned)(hy0 + 1) < (unsigned)HH);
            S_ER(0, ey, hx)     = ok0 ? fminf(S_HM(0, ey, hx), c0) : NINF;
            S_ER(1, ey, hx)     = ok0 ? fminf(S_HM(1, ey, hx), c1) : NINF;
            S_ER(0, ey + 1, hx) = ok1 ? fminf(c0, S_HM(0, ey + WIN + 1, hx)) : NINF;
            S_ER(1, ey + 1, hx) = ok1 ? fminf(c1, S_HM(1, ey + WIN + 1, hx)) : NINF;
        }
    }
    __syncthreads();   // s_hm dead -> BufB reusable as s_hx

    // Stage 4: horizontal max
    {
        constexpr int TPX2 = TPX / 2;
        for (int idx = tid; idx < EH * TPX2; idx += NT) {
            int ey = idx / TPX2;
            int xx = (idx - ey * TPX2) * 2;
            float c0 = S_ER(0, ey, xx + 1);
            float c1 = S_ER(1, ey, xx + 1);
#pragma unroll
            for (int dd = 2; dd <= WIN; ++dd) {
                c0 = fmaxf(c0, S_ER(0, ey, xx + dd));
                c1 = fmaxf(c1, S_ER(1, ey, xx + dd));
            }
            S_HX(0, ey, xx)     = fmaxf(S_ER(0, ey, xx), c0);
            S_HX(1, ey, xx)     = fmaxf(S_ER(1, ey, xx), c1);
            S_HX(0, ey, xx + 1) = fmaxf(c0, S_ER(0, ey, xx + WIN + 1));
            S_HX(1, ey, xx + 1) = fmaxf(c1, S_ER(1, ey, xx + WIN + 1));
        }
    }
    __syncthreads();

    // Stage 5: vertical max; f(w)=w/(w+eps); normalize centers; compose.
    {
        float wa = S_HX(0, tyy, 2 * txx), wb = S_HX(0, tyy, 2 * txx + 1);
        float wc = S_HX(1, tyy, 2 * txx), wd = S_HX(1, tyy, 2 * txx + 1);
#pragma unroll
        for (int dd = 1; dd <= WIN; ++dd) {
            wa = fmaxf(wa, S_HX(0, tyy + dd, 2 * txx));
            wb = fmaxf(wb, S_HX(0, tyy + dd, 2 * txx + 1));
            wc = fmaxf(wc, S_HX(1, tyy + dd, 2 * txx));
            wd = fmaxf(wd, S_HX(1, tyy + dd, 2 * txx + 1));
        }
        float m01a = wa / (wa + EPSF), m01b = wb / (wb + EPSF);
        float m10a = wc / (wc + EPSF), m10b = wd / (wd + EPSF);

        const float4* acc0 = reinterpret_cast<const float4*>(g_acc) + (size_t)(0 * BB + b) * HW;
        const float4* acc1 = reinterpret_cast<const float4*>(g_acc) + (size_t)(1 * BB + b) * HW;
        float4 a0a = acc0[p0], a0b = acc0[p0 + 1];
        float4 a1a = acc1[p0], a1b = acc1[p0 + 1];
        float i0a = 1.0f / (a0a.w + EPSF), i0b = 1.0f / (a0b.w + EPSF);
        float i1a = 1.0f / (a1a.w + EPSF), i1b = 1.0f / (a1b.w + EPSF);

        float f01r0 = a0a.x * i0a, f01r1 = a0b.x * i0b;
        float f01g0 = a0a.y * i0a, f01g1 = a0b.y * i0b;
        float f01b0 = a0a.z * i0a, f01b1 = a0b.z * i0b;
        float f10r0 = a1a.x * i1a, f10r1 = a1b.x * i1b;
        float f10g0 = a1a.y * i1a, f10g1 = a1b.y * i1b;
        float f10b0 = a1a.z * i1a, f10b1 = a1b.z * i1b;

        float* ob = out + (size_t)b * 18 * HW;
#define ST2(c, v0, v1) __stcs(reinterpret_cast<float2*>(&ob[(size_t)(c) * HW + p0]), make_float2(v0, v1))
        ST2(0,  m01a * f01r0 + (1.0f - m01a) * f10r0, m01b * f01r1 + (1.0f - m01b) * f10r1);
        ST2(1,  m01a * f01g0 + (1.0f - m01a) * f10g0, m01b * f01g1 + (1.0f - m01b) * f10g1);
        ST2(2,  m01a * f01b0 + (1.0f - m01a) * f10b0, m01b * f01b1 + (1.0f - m01b) * f10b1);
        ST2(3,  m10a * f10r0 + (1.0f - m10a) * f01r0, m10b * f10r1 + (1.0f - m10b) * f01r1);
        ST2(4,  m10a * f10g0 + (1.0f - m10a) * f01g0, m10b * f10g1 + (1.0f - m10b) * f01g1);
        ST2(5,  m10a * f10b0 + (1.0f - m10a) * f01b0, m10b * f10b1 + (1.0f - m10b) * f01b1);
        ST2(6,  f01r0, f01r1);
        ST2(7,  f01g0, f01g1);
        ST2(8,  f01b0, f01b1);
        ST2(9,  f10r0, f10r1);
        ST2(10, f10g0, f10g1);
        ST2(11, f10b0, f10b1);
        ST2(16, m01a, m01b);
        ST2(17, m10a, m10b);
#undef ST2
    }
#undef S_IN
#undef S_ER
#undef S_HM
#undef S_HX
}

__global__ void __launch_bounds__(NT, 4) open_compose_kernel(
    const int* __restrict__ kptr, int bIdx, float* __restrict__ out)
{
    extern __shared__ float Dyn[];
    float* BufA = Dyn;
    float* BufB = Dyn + NIN_F;

    int kk = kptr[0];
    int r = (kk >= 2) ? (kk - 1) / 2 : 0;
    if (r > RMAX) r = RMAX;

    switch (r) {
        case 0: open_body<0>(BufA, BufB, bIdx, out); break;
        case 1: open_body<1>(BufA, BufB, bIdx, out); break;
        case 2: open_body<2>(BufA, BufB, bIdx, out); break;
        case 3: open_body<3>(BufA, BufB, bIdx, out); break;
        default: open_body<4>(BufA, BufB, bIdx, out); break;
    }
}

// ---------------------------------------------------------------------------
extern "C" void kernel_launch(void* const* d_in, const int* in_sizes, int n_in,
                              void* d_out, int out_size)
{
    const float* img0  = (const float*)d_in[0];
    const float* img1  = (const float*)d_in[1];
    const float* flow0 = (const float*)d_in[2];
    const float* flow1 = (const float*)d_in[3];
    const float* z0    = (const float*)d_in[4];
    const float* z1    = (const float*)d_in[5];
    const int*   kptr  = (const int*)d_in[6];
    float* out = (float*)d_out;

    static cudaStream_t s1 = nullptr, sC = nullptr;
    static cudaEvent_t evFork = nullptr, evMb0 = nullptr, evMb1 = nullptr,
                       evSb0 = nullptr, evJoin1 = nullptr, evJoinC = nullptr;
    if (s1 == nullptr) {
        cudaStreamCreateWithFlags(&s1, cudaStreamNonBlocking);
        cudaStreamCreateWithFlags(&sC, cudaStreamNonBlocking);
        cudaEventCreateWithFlags(&evFork, cudaEventDisableTiming);
        cudaEventCreateWithFlags(&evMb0, cudaEventDisableTiming);
        cudaEventCreateWithFlags(&evMb1, cudaEventDisableTiming);
        cudaEventCreateWithFlags(&evSb0, cudaEventDisableTiming);
        cudaEventCreateWithFlags(&evJoin1, cudaEventDisableTiming);
        cudaEventCreateWithFlags(&evJoinC, cudaEventDisableTiming);
        cudaFuncSetAttribute(open_compose_kernel,
                             cudaFuncAttributeMaxDynamicSharedMemorySize,
                             DYN_SMEM_BYTES);
    }

    void* accPtr = nullptr;
    cudaGetSymbolAddress(&accPtr, g_acc);
    float4* acc = reinterpret_cast<float4*>(accPtr);
    // chunk layout: [d0b0][d0b1][d1b0][d1b1], each HW float4s
    float4* acc_d0b0 = acc + 0 * (size_t)HW;
    float4* acc_d0b1 = acc + 1 * (size_t)HW;
    float4* acc_d1b0 = acc + 2 * (size_t)HW;
    float4* acc_d1b1 = acc + 3 * (size_t)HW;
    const size_t chunkBytes = (size_t)HW * sizeof(float4);

    int threads = 256;
    int blocksHW = (HW + threads - 1) / threads;
    dim3 gblk(TBX, TTY, 1);
    dim3 ggrid(WW / TPX, HH / TTY, 1);

    cudaEventRecord(evFork, 0);
    cudaStreamWaitEvent(s1, evFork, 0);
    cudaStreamWaitEvent(sC, evFork, 0);

    // Stream0: clear batch-0 chunks, then splat batch 0 (both dirs).
    cudaMemsetAsync(acc_d0b0, 0, chunkBytes, 0);
    cudaMemsetAsync(acc_d1b0, 0, chunkBytes, 0);
    cudaEventRecord(evMb0, 0);
    splat_batch_kernel<<<blocksHW, threads, 0, 0>>>(
        img0, flow1, z1, acc_d0b0,
        img1, flow0, z0, acc_d1b0);
    cudaEventRecord(evSb0, 0);

    // s1: clear batch-1 chunks under splat_b0's window; then splat batch 1
    // AFTER splat_b0 completes (serialized REDG; frees stream0 for open_b0).
    cudaStreamWaitEvent(s1, evMb0, 0);
    cudaMemsetAsync(acc_d0b1, 0, chunkBytes, s1);
    cudaMemsetAsync(acc_d1b1, 0, chunkBytes, s1);
    cudaEventRecord(evMb1, s1);
    cudaStreamWaitEvent(s1, evSb0, 0);
    splat_batch_kernel<<<blocksHW, threads, 0, s1>>>(
        img0 + (size_t)3 * HW, flow1 + (size_t)2 * HW, z1 + (size_t)HW, acc_d0b1,
        img1 + (size_t)3 * HW, flow0 + (size_t)2 * HW, z0 + (size_t)HW, acc_d1b1);
    cudaEventRecord(evJoin1, s1);

    // sC: flow-copy under the splat windows.
    cudaStreamWaitEvent(sC, evMb1, 0);
    {
        int fblocks = (FQ + threads - 1) / threads;
        flow_copy_kernel<<<fblocks, threads, 0, sC>>>(
            reinterpret_cast<const float4*>(flow0),
            reinterpret_cast<const float4*>(flow1),
            reinterpret_cast<float4*>(out));
        cudaEventRecord(evJoinC, sC);
    }

    // Stream0: open batch 0 — concurrent with splat batch 1.
    open_compose_kernel<<<ggrid, gblk, DYN_SMEM_BYTES, 0>>>(kptr, 0, out);

    // Stream0: open batch 1 after splat batch 1 completes.
    cudaStreamWaitEvent(0, evJoin1, 0);
    open_compose_kernel<<<ggrid, gblk, DYN_SMEM_BYTES, 0>>>(kptr, 1, out);

    // Join flow-copy before capture end (disjoint outputs; no hazard)
    cudaStreamWaitEvent(0, evJoinC, 0);
}